// round 1
// baseline (speedup 1.0000x reference)
#include <cuda_runtime.h>
#include <math.h>

// ---------------------------------------------------------------------------
// TextureBaker: for each bake pixel (pixel-center UV), find the lowest-index
// triangle containing it (barycentric test, with degenerate-triangle guard),
// then interpolate per-vertex attributes with the barycentric weights.
//
// Two kernels:
//   1) setup_kernel: per-triangle precompute (a, v0, v1, d00, d01, d11,
//      1/denom [NaN if degenerate], vertex ids) -> __device__ globals.
//   2) bake_kernel: blocks copy the setup into shared memory (coalesced),
//      each thread owns one pixel and scans triangles in index order with
//      early exit on first hit; then gathers attr and blends.
// ---------------------------------------------------------------------------

#define MAX_F 8192

__device__ float g_ax [MAX_F];
__device__ float g_ay [MAX_F];
__device__ float g_v0x[MAX_F];
__device__ float g_v0y[MAX_F];
__device__ float g_v1x[MAX_F];
__device__ float g_v1y[MAX_F];
__device__ float g_d00[MAX_F];
__device__ float g_d01[MAX_F];
__device__ float g_d11[MAX_F];
__device__ float g_inv[MAX_F];
__device__ int   g_i0 [MAX_F];
__device__ int   g_i1 [MAX_F];
__device__ int   g_i2 [MAX_F];

__global__ void tb_setup_kernel(const float* __restrict__ uv,
                                const int*   __restrict__ fidx,
                                int nf)
{
    int t = blockIdx.x * blockDim.x + threadIdx.x;
    if (t >= nf) return;

    int i0 = fidx[3 * t + 0];
    int i1 = fidx[3 * t + 1];
    int i2 = fidx[3 * t + 2];

    float ax = uv[2 * i0],     ay = uv[2 * i0 + 1];
    float bx = uv[2 * i1],     by = uv[2 * i1 + 1];
    float cx = uv[2 * i2],     cy = uv[2 * i2 + 1];

    float v0x = bx - ax, v0y = by - ay;
    float v1x = cx - ax, v1y = cy - ay;

    float d00 = v0x * v0x + v0y * v0y;
    float d01 = v0x * v1x + v0y * v1y;
    float d11 = v1x * v1x + v1y * v1y;
    float denom = d00 * d11 - d01 * d01;

    // Degenerate triangle: reference forces bary = -1 (never inside).
    // NaN makes every comparison in the inside-test false -> same behavior.
    float inv = (fabsf(denom) < 1e-12f) ? __int_as_float(0x7fc00000)
                                        : (1.0f / denom);

    g_ax [t] = ax;  g_ay [t] = ay;
    g_v0x[t] = v0x; g_v0y[t] = v0y;
    g_v1x[t] = v1x; g_v1y[t] = v1y;
    g_d00[t] = d00; g_d01[t] = d01; g_d11[t] = d11;
    g_inv[t] = inv;
    g_i0 [t] = i0;  g_i1 [t] = i1;  g_i2 [t] = i2;
}

__global__ void __launch_bounds__(256)
tb_bake_kernel(const float* __restrict__ attr,
               int nf, int res,
               float* __restrict__ out)
{
    extern __shared__ float s[];
    float* s_ax  = s;
    float* s_ay  = s + 1 * nf;
    float* s_v0x = s + 2 * nf;
    float* s_v0y = s + 3 * nf;
    float* s_v1x = s + 4 * nf;
    float* s_v1y = s + 5 * nf;
    float* s_d00 = s + 6 * nf;
    float* s_d01 = s + 7 * nf;
    float* s_d11 = s + 8 * nf;
    float* s_inv = s + 9 * nf;
    int*   s_i0  = (int*)(s + 10 * nf);
    int*   s_i1  = s_i0 + nf;
    int*   s_i2  = s_i1 + nf;

    for (int j = threadIdx.x; j < nf; j += blockDim.x) {
        s_ax [j] = g_ax [j];
        s_ay [j] = g_ay [j];
        s_v0x[j] = g_v0x[j];
        s_v0y[j] = g_v0y[j];
        s_v1x[j] = g_v1x[j];
        s_v1y[j] = g_v1y[j];
        s_d00[j] = g_d00[j];
        s_d01[j] = g_d01[j];
        s_d11[j] = g_d11[j];
        s_inv[j] = g_inv[j];
        s_i0 [j] = g_i0 [j];
        s_i1 [j] = g_i1 [j];
        s_i2 [j] = g_i2 [j];
    }
    __syncthreads();

    int pix = blockIdx.x * blockDim.x + threadIdx.x;
    int npix = res * res;
    if (pix >= npix) return;

    int row = pix / res;
    int col = pix - row * res;

    // pixel-center UV; x = u along columns, y = v along rows
    float resf = (float)res;
    float pxx = ((float)col + 0.5f) / resf;
    float pxy = ((float)row + 0.5f) / resf;

    int   hit = -1;
    float u = 0.0f, v = 0.0f, w = 0.0f;

    // First (lowest-index) containing triangle wins -> early exit.
    for (int j = 0; j < nf; j++) {
        float v2x = pxx - s_ax[j];
        float v2y = pxy - s_ay[j];
        float d20 = v2x * s_v0x[j] + v2y * s_v0y[j];
        float d21 = v2x * s_v1x[j] + v2y * s_v1y[j];
        float inv = s_inv[j];
        float vv  = (s_d11[j] * d20 - s_d01[j] * d21) * inv;
        float ww  = (s_d00[j] * d21 - s_d01[j] * d20) * inv;
        float uu  = 1.0f - vv - ww;
        if (uu >= 0.0f && vv >= 0.0f && ww >= 0.0f) {
            hit = j; u = uu; v = vv; w = ww;
            break;
        }
    }

    float o0 = 0.0f, o1 = 0.0f, o2 = 0.0f;
    if (hit >= 0) {
        int i0 = s_i0[hit];
        int i1 = s_i1[hit];
        int i2 = s_i2[hit];
        const float* a0 = attr + 3 * i0;
        const float* a1 = attr + 3 * i1;
        const float* a2 = attr + 3 * i2;
        o0 = u * a0[0] + v * a1[0] + w * a2[0];
        o1 = u * a0[1] + v * a1[1] + w * a2[1];
        o2 = u * a0[2] + v * a1[2] + w * a2[2];
    }

    out[3 * pix + 0] = o0;
    out[3 * pix + 1] = o1;
    out[3 * pix + 2] = o2;
}

extern "C" void kernel_launch(void* const* d_in, const int* in_sizes, int n_in,
                              void* d_out, int out_size)
{
    const float* attr = (const float*)d_in[0];
    const float* uv   = (const float*)d_in[1];
    const int*   fidx = (const int*)  d_in[2];
    float*       out  = (float*)      d_out;

    int nf = in_sizes[2] / 3;
    // Reference truncates to a multiple of the chunk size (64).
    int nf_used = (nf / 64) * 64;
    if (nf_used > MAX_F) nf_used = MAX_F;

    // res from out_size = res*res*3
    int res = (int)(sqrt((double)out_size / 3.0) + 0.5);
    int npix = res * res;

    if (nf_used > 0) {
        int sblocks = (nf_used + 255) / 256;
        tb_setup_kernel<<<sblocks, 256>>>(uv, fidx, nf_used);
    }

    size_t smem = (size_t)nf_used * (10 * sizeof(float) + 3 * sizeof(int));
    int bblocks = (npix + 255) / 256;
    tb_bake_kernel<<<bblocks, 256, smem>>>(attr, nf_used, res, out);
}

// round 2
// speedup vs baseline: 5.4848x; 5.4848x over previous
#include <cuda_runtime.h>
#include <math.h>

// ---------------------------------------------------------------------------
// TextureBaker with tile binning:
//   1) tb_setup : per-triangle precompute -> AoS records (64B).
//   2) tb_bin   : per 16x16-pixel tile, conservative triangle/tile SAT test,
//                 stable (index-ordered) compaction into per-tile lists.
//   3) tb_bake  : block = tile; gather listed triangle records into smem,
//                 per-pixel first-hit scan (early exit) + attr interpolation.
// Inner-loop arithmetic kept expression-identical to the passing R1 kernel.
// ---------------------------------------------------------------------------

#define MAX_F     8192
#define TS        16           // tile size in pixels
#define NTILE_MAX 16384
#define LIST_CAP  (8*1024*1024)
#define SMEM_CAP  512          // triangle records per smem batch

struct __align__(16) Tri {
    float ax, ay, v0x, v0y;
    float v1x, v1y, d00, d01;
    float d11, inv;
    int   i0,  i1;
    int   i2,  pad0, pad1, pad2;
};

__device__ Tri g_tri[MAX_F];
__device__ int g_list[LIST_CAP];
__device__ int g_count[NTILE_MAX];

// ------------------------------- setup ------------------------------------
__global__ void tb_setup_kernel(const float* __restrict__ uv,
                                const int*   __restrict__ fidx,
                                int nf)
{
    int t = blockIdx.x * blockDim.x + threadIdx.x;
    if (t >= nf) return;

    int i0 = fidx[3 * t + 0];
    int i1 = fidx[3 * t + 1];
    int i2 = fidx[3 * t + 2];

    float ax = uv[2 * i0], ay = uv[2 * i0 + 1];
    float bx = uv[2 * i1], by = uv[2 * i1 + 1];
    float cx = uv[2 * i2], cy = uv[2 * i2 + 1];

    float v0x = bx - ax, v0y = by - ay;
    float v1x = cx - ax, v1y = cy - ay;

    float d00 = v0x * v0x + v0y * v0y;
    float d01 = v0x * v1x + v0y * v1y;
    float d11 = v1x * v1x + v1y * v1y;
    float denom = d00 * d11 - d01 * d01;

    // Degenerate triangle -> NaN inv -> inside test always false (matches ref).
    float inv = (fabsf(denom) < 1e-12f) ? __int_as_float(0x7fc00000)
                                        : (1.0f / denom);

    Tri r;
    r.ax = ax;  r.ay = ay;  r.v0x = v0x; r.v0y = v0y;
    r.v1x = v1x; r.v1y = v1y; r.d00 = d00; r.d01 = d01;
    r.d11 = d11; r.inv = inv;
    r.i0 = i0; r.i1 = i1; r.i2 = i2;
    r.pad0 = r.pad1 = r.pad2 = 0;
    g_tri[t] = r;
}

// ------------------------------- binning ----------------------------------
__device__ __forceinline__ bool rect_outside_edge(
    float px, float py, float qx, float qy, float rx, float ry,
    float x0, float y0, float x1, float y1)
{
    float ex = qx - px, ey = qy - py;
    float sr  = ex * (ry - py) - ey * (rx - px);
    float s00 = ex * (y0 - py) - ey * (x0 - px);
    float s01 = ex * (y1 - py) - ey * (x0 - px);
    float s10 = ex * (y0 - py) - ey * (x1 - px);
    float s11 = ex * (y1 - py) - ey * (x1 - px);
    float mx = fmaxf(fmaxf(s00, s01), fmaxf(s10, s11));
    float mn = fminf(fminf(s00, s01), fminf(s10, s11));
    if (sr > 0.0f) return mx < 0.0f;   // whole rect strictly on far side
    if (sr < 0.0f) return mn > 0.0f;
    return false;                      // degenerate edge: keep (conservative)
}

__global__ void __launch_bounds__(256)
tb_bin_kernel(int nf, int res, int ntx)
{
    int tile = blockIdx.x;
    int tx = tile % ntx;
    int ty = tile / ntx;

    const float eps = 1e-5f;
    float rinv = 1.0f / (float)res;
    float x0 = (float)(tx * TS)      * rinv - eps;
    float x1 = (float)(tx * TS + TS) * rinv + eps;
    float y0 = (float)(ty * TS)      * rinv - eps;
    float y1 = (float)(ty * TS + TS) * rinv + eps;

    __shared__ int s_warpTot[8];
    __shared__ int s_base;
    int tid  = threadIdx.x;
    int lane = tid & 31;
    int wid  = tid >> 5;
    if (tid == 0) s_base = 0;
    __syncthreads();

    int listBase = tile * nf;

    for (int chunk = 0; chunk < nf; chunk += 256) {
        int t = chunk + tid;
        bool keep = false;
        if (t < nf) {
            Tri r = g_tri[t];
            float ax = r.ax,        ay = r.ay;
            float bx = ax + r.v0x,  by = ay + r.v0y;
            float cx = ax + r.v1x,  cy = ay + r.v1y;

            float tminx = fminf(ax, fminf(bx, cx));
            float tmaxx = fmaxf(ax, fmaxf(bx, cx));
            float tminy = fminf(ay, fminf(by, cy));
            float tmaxy = fmaxf(ay, fmaxf(by, cy));

            keep = !(tminx > x1 || tmaxx < x0 || tminy > y1 || tmaxy < y0);
            if (keep) {
                if (rect_outside_edge(ax, ay, bx, by, cx, cy, x0, y0, x1, y1) ||
                    rect_outside_edge(bx, by, cx, cy, ax, ay, x0, y0, x1, y1) ||
                    rect_outside_edge(cx, cy, ax, ay, bx, by, x0, y0, x1, y1))
                    keep = false;
            }
        }

        unsigned bal = __ballot_sync(0xffffffffu, keep);
        int wpre = __popc(bal & ((1u << lane) - 1u));
        if (lane == 0) s_warpTot[wid] = __popc(bal);
        __syncthreads();

        int wbase = 0;
        #pragma unroll
        for (int k = 0; k < 8; k++) wbase += (k < wid) ? s_warpTot[k] : 0;

        if (keep)
            g_list[listBase + s_base + wbase + wpre] = t;
        __syncthreads();

        if (tid == 0) {
            int tot = 0;
            #pragma unroll
            for (int k = 0; k < 8; k++) tot += s_warpTot[k];
            s_base += tot;
        }
        __syncthreads();
    }

    if (tid == 0) g_count[tile] = s_base;
}

// -------------------------------- bake ------------------------------------
__global__ void __launch_bounds__(256)
tb_bake_kernel(const float* __restrict__ attr,
               int nf, int res, int ntx,
               float* __restrict__ out)
{
    extern __shared__ Tri s_tri[];

    int tile = blockIdx.x;
    int tx = tile % ntx;
    int ty = tile / ntx;
    int tid = threadIdx.x;

    int col = tx * TS + (tid & (TS - 1));
    int row = ty * TS + (tid >> 4);
    bool valid = (col < res) && (row < res);

    float rinv = 1.0f / (float)res;
    float pxx = ((float)col + 0.5f) * rinv;
    float pxy = ((float)row + 0.5f) * rinv;

    int count = g_count[tile];
    int listBase = tile * nf;

    int   hitI0 = -1, hitI1 = 0, hitI2 = 0;
    float u = 0.0f, v = 0.0f, w = 0.0f;
    bool  found = false;

    for (int batch = 0; batch < count; batch += SMEM_CAP) {
        int bn = min(SMEM_CAP, count - batch);

        __syncthreads();
        for (int e = tid; e < bn; e += 256) {
            int t = g_list[listBase + batch + e];
            const float4* src = (const float4*)&g_tri[t];
            float4* dst = (float4*)&s_tri[e];
            dst[0] = src[0]; dst[1] = src[1];
            dst[2] = src[2]; dst[3] = src[3];
        }
        __syncthreads();

        if (!found && valid) {
            for (int j = 0; j < bn; j++) {
                float4 q0 = *(const float4*)&s_tri[j].ax;   // ax ay v0x v0y
                float4 q1 = *(const float4*)&s_tri[j].v1x;  // v1x v1y d00 d01
                float2 q2 = *(const float2*)&s_tri[j].d11;  // d11 inv

                float v2x = pxx - q0.x;
                float v2y = pxy - q0.y;
                float d20 = v2x * q0.z + v2y * q0.w;
                float d21 = v2x * q1.x + v2y * q1.y;
                float vv  = (q2.x * d20 - q1.w * d21) * q2.y;
                float ww  = (q1.z * d21 - q1.w * d20) * q2.y;
                float uu  = 1.0f - vv - ww;
                if (uu >= 0.0f && vv >= 0.0f && ww >= 0.0f) {
                    found = true;
                    u = uu; v = vv; w = ww;
                    hitI0 = s_tri[j].i0;
                    hitI1 = s_tri[j].i1;
                    hitI2 = s_tri[j].i2;
                    break;
                }
            }
        }
    }

    if (!valid) return;

    float o0 = 0.0f, o1 = 0.0f, o2 = 0.0f;
    if (found) {
        const float* a0 = attr + 3 * hitI0;
        const float* a1 = attr + 3 * hitI1;
        const float* a2 = attr + 3 * hitI2;
        o0 = u * a0[0] + v * a1[0] + w * a2[0];
        o1 = u * a0[1] + v * a1[1] + w * a2[1];
        o2 = u * a0[2] + v * a1[2] + w * a2[2];
    }

    int pix = row * res + col;
    out[3 * pix + 0] = o0;
    out[3 * pix + 1] = o1;
    out[3 * pix + 2] = o2;
}

// ------------------------------- launch -----------------------------------
extern "C" void kernel_launch(void* const* d_in, const int* in_sizes, int n_in,
                              void* d_out, int out_size)
{
    const float* attr = (const float*)d_in[0];
    const float* uv   = (const float*)d_in[1];
    const int*   fidx = (const int*)  d_in[2];
    float*       out  = (float*)      d_out;

    int nf = in_sizes[2] / 3;
    int nf_used = (nf / 64) * 64;          // reference truncates to chunk of 64
    if (nf_used > MAX_F) nf_used = MAX_F;

    int res = (int)(sqrt((double)out_size / 3.0) + 0.5);
    int ntx = (res + TS - 1) / TS;
    int nty = ntx;
    int ntiles = ntx * nty;

    if (nf_used > 0) {
        int sblocks = (nf_used + 255) / 256;
        tb_setup_kernel<<<sblocks, 256>>>(uv, fidx, nf_used);
        tb_bin_kernel<<<ntiles, 256>>>(nf_used, res, ntx);
    } else {
        // still need counts zeroed; bin kernel handles nf=0 too
        tb_bin_kernel<<<ntiles, 256>>>(0, res, ntx);
    }

    size_t smem = (size_t)SMEM_CAP * sizeof(Tri);
    tb_bake_kernel<<<ntiles, 256, smem>>>(attr, nf_used, res, ntx, out);
}